// round 2
// baseline (speedup 1.0000x reference)
#include <cuda_runtime.h>
#include <cstdint>

// Problem constants (fixed shapes from the reference)
#define M_NODES 150000      // 3 * NATOMS
#define NE_EDGES 1500000
#define NHEADS 4
#define DHEAD 16

// Device-global scratch (allocation-free rule: statics are allowed)
__device__ float g_qkv[M_NODES * 64];   // 38.4 MB  (fits in L2)
__device__ float g_wV [M_NODES * 64];   // 38.4 MB
__device__ float g_Z  [M_NODES * NHEADS];
__device__ int   g_idx_is_64;           // 1 if edge_index is int64, else int32

__device__ __forceinline__ float elu1(float v) {
    return v > 0.0f ? v : expm1f(v);
}

// Vector reduction: 16B atomic add to global (sm_90+)
__device__ __forceinline__ void red_add_v4(float* addr, float4 v) {
    asm volatile("red.global.add.v4.f32 [%0], {%1, %2, %3, %4};"
                 :: "l"(addr), "f"(v.x), "f"(v.y), "f"(v.z), "f"(v.w)
                 : "memory");
}

// ---------------------------------------------------------------------------
// Probe: decide whether edge_index buffer holds int64 or int32.
// If int64 with values < 2^31, odd int32 words are all zero.
// ---------------------------------------------------------------------------
__global__ void probe_idx_kernel(const int* __restrict__ ei32) {
    int z = (ei32[1] == 0) & (ei32[3] == 0) & (ei32[5] == 0) & (ei32[7] == 0);
    g_idx_is_64 = z;
}

// ---------------------------------------------------------------------------
// Kernel A: per-node qkv = ((elu(x*W1+b1)) @ W2 + b2) @ W + b; zero accumulators
// ---------------------------------------------------------------------------
__global__ __launch_bounds__(256)
void qkv_kernel(const float* __restrict__ ev,
                const float* __restrict__ W1, const float* __restrict__ b1,
                const float* __restrict__ W2, const float* __restrict__ b2,
                const float* __restrict__ W,  const float* __restrict__ b) {
    __shared__ float sW1[4], sb1[4], sW2[64], sb2[16], sW[1024], sb[64];
    int t = threadIdx.x;
    if (t < 4)  { sW1[t] = W1[t]; sb1[t] = b1[t]; }
    if (t < 64) { sW2[t] = W2[t]; sb[t] = b[t]; }
    if (t < 16) { sb2[t] = b2[t]; }
    for (int i = t; i < 1024; i += blockDim.x) sW[i] = W[i];
    __syncthreads();

    int m = blockIdx.x * blockDim.x + t;
    if (m >= M_NODES) return;

    float x = ev[m];

    float t4[4];
#pragma unroll
    for (int j = 0; j < 4; j++) t4[j] = elu1(fmaf(x, sW1[j], sb1[j]));

    float h16[16];
#pragma unroll
    for (int k = 0; k < 16; k++) {
        float v = sb2[k];
#pragma unroll
        for (int j = 0; j < 4; j++) v = fmaf(t4[j], sW2[j * 16 + k], v);
        h16[k] = v;
    }

    float4* q4 = reinterpret_cast<float4*>(g_qkv + (size_t)m * 64);
    float4* w4 = reinterpret_cast<float4*>(g_wV  + (size_t)m * 64);
#pragma unroll
    for (int c4 = 0; c4 < 16; c4++) {
        float o[4];
#pragma unroll
        for (int u = 0; u < 4; u++) {
            int c = c4 * 4 + u;
            float v = sb[c];
#pragma unroll
            for (int k = 0; k < 16; k++) v = fmaf(h16[k], sW[k * 64 + c], v);
            o[u] = v;
        }
        q4[c4] = make_float4(o[0], o[1], o[2], o[3]);
        w4[c4] = make_float4(0.f, 0.f, 0.f, 0.f);
    }
    reinterpret_cast<float4*>(g_Z)[m] = make_float4(0.f, 0.f, 0.f, 0.f);
}

// ---------------------------------------------------------------------------
// Kernel B: one thread per (edge, head). Compute E_head on the fly, gather
// src/dst qkv heads from L2-resident table, score, scatter with vector REDs.
// ---------------------------------------------------------------------------
__global__ __launch_bounds__(256)
void edge_kernel(const void* __restrict__ ei_raw,
                 const float* __restrict__ ef,
                 const float* __restrict__ W2, const float* __restrict__ b2,
                 const float* __restrict__ W,  const float* __restrict__ b) {
    __shared__ float sW2[64], sb2[16], sW[1024], sb[64];
    int t = threadIdx.x;
    if (t < 64) { sW2[t] = W2[t]; sb[t] = b[t]; }
    if (t < 16) { sb2[t] = b2[t]; }
    for (int i = t; i < 1024; i += blockDim.x) sW[i] = W[i];
    __syncthreads();

    long long gi = (long long)blockIdx.x * blockDim.x + t;
    if (gi >= (long long)NE_EDGES * NHEADS) return;
    int e    = (int)(gi >> 2);
    int head = (int)(gi & 3);

    int src, dst;
    if (g_idx_is_64) {
        const long long* ei = (const long long*)ei_raw;
        src = (int)__ldg(ei + e);
        dst = (int)__ldg(ei + NE_EDGES + e);
    } else {
        const int* ei = (const int*)ei_raw;
        src = __ldg(ei + e);
        dst = __ldg(ei + NE_EDGES + e);
    }

    float4 f = __ldg(reinterpret_cast<const float4*>(ef) + e);
    float efv[4] = {f.x, f.y, f.z, f.w};

    // e16 = elu(edge_feature @ W2 + b2)
    float e16[16];
#pragma unroll
    for (int k = 0; k < 16; k++) {
        float v = sb2[k];
#pragma unroll
        for (int j = 0; j < 4; j++) v = fmaf(efv[j], sW2[j * 16 + k], v);
        e16[k] = elu1(v);
    }

    // E_head = e16 @ W[:, head*16 : head*16+16] + b[head*16 ...]
    float Eh[16];
    const float* Wh = sW + head * 16;
    const float* bh = sb + head * 16;
#pragma unroll
    for (int d = 0; d < 16; d++) {
        float v = bh[d];
#pragma unroll
        for (int k = 0; k < 16; k++) v = fmaf(e16[k], Wh[k * 64 + d], v);
        Eh[d] = v;
    }

    // Gather src/dst qkv head slices (64 B each, L2-resident)
    const float4* sq = reinterpret_cast<const float4*>(g_qkv + (size_t)src * 64 + head * 16);
    const float4* dq = reinterpret_cast<const float4*>(g_qkv + (size_t)dst * 64 + head * 16);
    float4 s0 = __ldg(sq + 0), s1 = __ldg(sq + 1), s2 = __ldg(sq + 2), s3 = __ldg(sq + 3);
    float4 q0 = __ldg(dq + 0), q1 = __ldg(dq + 1), q2 = __ldg(dq + 2), q3 = __ldg(dq + 3);

    float sc = 0.f;
    sc = fmaf(s0.x * q0.x, Eh[ 0], sc); sc = fmaf(s0.y * q0.y, Eh[ 1], sc);
    sc = fmaf(s0.z * q0.z, Eh[ 2], sc); sc = fmaf(s0.w * q0.w, Eh[ 3], sc);
    sc = fmaf(s1.x * q1.x, Eh[ 4], sc); sc = fmaf(s1.y * q1.y, Eh[ 5], sc);
    sc = fmaf(s1.z * q1.z, Eh[ 6], sc); sc = fmaf(s1.w * q1.w, Eh[ 7], sc);
    sc = fmaf(s2.x * q2.x, Eh[ 8], sc); sc = fmaf(s2.y * q2.y, Eh[ 9], sc);
    sc = fmaf(s2.z * q2.z, Eh[10], sc); sc = fmaf(s2.w * q2.w, Eh[11], sc);
    sc = fmaf(s3.x * q3.x, Eh[12], sc); sc = fmaf(s3.y * q3.y, Eh[13], sc);
    sc = fmaf(s3.z * q3.z, Eh[14], sc); sc = fmaf(s3.w * q3.w, Eh[15], sc);

    sc *= 0.25f;                                  // 1/sqrt(16)
    sc = fminf(fmaxf(sc, -5.0f), 5.0f);
    float w = __expf(sc);

    float* dw = g_wV + (size_t)dst * 64 + head * 16;
    red_add_v4(dw +  0, make_float4(s0.x * w, s0.y * w, s0.z * w, s0.w * w));
    red_add_v4(dw +  4, make_float4(s1.x * w, s1.y * w, s1.z * w, s1.w * w));
    red_add_v4(dw +  8, make_float4(s2.x * w, s2.y * w, s2.z * w, s2.w * w));
    red_add_v4(dw + 12, make_float4(s3.x * w, s3.y * w, s3.z * w, s3.w * w));
    atomicAdd(g_Z + (size_t)dst * NHEADS + head, w);
}

// ---------------------------------------------------------------------------
// Kernel C: h = wV/(Z+1e-6); out = elu(h @ Wout + bout) @ Wout1 + bout1
// ---------------------------------------------------------------------------
__global__ __launch_bounds__(256)
void out_kernel(float* __restrict__ out,
                const float* __restrict__ Wout,  const float* __restrict__ bout,
                const float* __restrict__ Wout1, const float* __restrict__ bout1) {
    __shared__ float sWo[1024], sbo[16], sW1[16], sb1;
    int t = threadIdx.x;
    for (int i = t; i < 1024; i += blockDim.x) sWo[i] = Wout[i];
    if (t < 16) { sbo[t] = bout[t]; sW1[t] = Wout1[t]; }
    if (t == 0) sb1 = bout1[0];
    __syncthreads();

    int m = blockIdx.x * blockDim.x + t;
    if (m >= M_NODES) return;

    float4 zf = reinterpret_cast<const float4*>(g_Z)[m];
    float rz[4] = {1.0f / (zf.x + 1e-6f), 1.0f / (zf.y + 1e-6f),
                   1.0f / (zf.z + 1e-6f), 1.0f / (zf.w + 1e-6f)};

    float acc[16];
#pragma unroll
    for (int k = 0; k < 16; k++) acc[k] = sbo[k];

    const float4* wv4 = reinterpret_cast<const float4*>(g_wV + (size_t)m * 64);
#pragma unroll
    for (int c4 = 0; c4 < 16; c4++) {
        float4 v = wv4[c4];
        float r = rz[c4 >> 2];
        float hv[4] = {v.x * r, v.y * r, v.z * r, v.w * r};
#pragma unroll
        for (int u = 0; u < 4; u++) {
            int c = c4 * 4 + u;
#pragma unroll
            for (int k = 0; k < 16; k++) acc[k] = fmaf(hv[u], sWo[c * 16 + k], acc[k]);
        }
    }

    float val = sb1;
#pragma unroll
    for (int k = 0; k < 16; k++) {
        float a = elu1(acc[k]);
        val = fmaf(a, sW1[k], val);
    }
    out[m] = val;
}

// ---------------------------------------------------------------------------
extern "C" void kernel_launch(void* const* d_in, const int* in_sizes, int n_in,
                              void* d_out, int out_size) {
    // metadata order: node_attr, edge_index, edge_feature, edge_vector,
    //                 W1, b1, W2, b2, W, b, Wout, bout, Wout1, bout1
    const void*  ei   = d_in[1];
    const float* ef   = (const float*)d_in[2];
    const float* ev   = (const float*)d_in[3];
    const float* W1   = (const float*)d_in[4];
    const float* b1   = (const float*)d_in[5];
    const float* W2   = (const float*)d_in[6];
    const float* b2   = (const float*)d_in[7];
    const float* W    = (const float*)d_in[8];
    const float* b    = (const float*)d_in[9];
    const float* Wout = (const float*)d_in[10];
    const float* bout = (const float*)d_in[11];
    const float* Wout1= (const float*)d_in[12];
    const float* bout1= (const float*)d_in[13];
    float* out = (float*)d_out;

    probe_idx_kernel<<<1, 1>>>((const int*)ei);

    qkv_kernel<<<(M_NODES + 255) / 256, 256>>>(ev, W1, b1, W2, b2, W, b);

    long long nwork = (long long)NE_EDGES * NHEADS;
    int nblk = (int)((nwork + 255) / 256);
    edge_kernel<<<nblk, 256>>>(ei, ef, W2, b2, W, b);

    out_kernel<<<(M_NODES + 255) / 256, 256>>>(out, Wout, bout, Wout1, bout1);
}

// round 3
// speedup vs baseline: 1.2059x; 1.2059x over previous
#include <cuda_runtime.h>
#include <cstdint>

// Problem constants (fixed shapes from the reference)
#define M_NODES 150000      // 3 * NATOMS
#define NE_EDGES 1500000
#define NHEADS 4
#define DHEAD 16

// Device-global scratch (allocation-free rule: statics are allowed)
__device__ float g_qkv[M_NODES * 64];   // 38.4 MB  (fits in L2)
__device__ float g_wV [M_NODES * 64];   // 38.4 MB
__device__ float g_Z  [M_NODES * NHEADS];
__device__ int   g_idx_is_64;           // 1 if edge_index is int64, else int32

__device__ __forceinline__ float elu1(float v) {
    return v > 0.0f ? v : (__expf(v) - 1.0f);
}

// Vector reduction: 16B atomic add to global (sm_90+)
__device__ __forceinline__ void red_add_v4(float* addr, float4 v) {
    asm volatile("red.global.add.v4.f32 [%0], {%1, %2, %3, %4};"
                 :: "l"(addr), "f"(v.x), "f"(v.y), "f"(v.z), "f"(v.w)
                 : "memory");
}

// ---------------------------------------------------------------------------
// Probe: decide whether edge_index buffer holds int64 or int32.
// If int64 with values < 2^31, odd int32 words are all zero.
// ---------------------------------------------------------------------------
__global__ void probe_idx_kernel(const int* __restrict__ ei32) {
    int z = (ei32[1] == 0) & (ei32[3] == 0) & (ei32[5] == 0) & (ei32[7] == 0);
    g_idx_is_64 = z;
}

// ---------------------------------------------------------------------------
// Kernel A: per-node qkv = ((elu(x*W1+b1)) @ W2 + b2) @ W + b; zero accumulators
// ---------------------------------------------------------------------------
__global__ __launch_bounds__(256)
void qkv_kernel(const float* __restrict__ ev,
                const float* __restrict__ W1, const float* __restrict__ b1,
                const float* __restrict__ W2, const float* __restrict__ b2,
                const float* __restrict__ W,  const float* __restrict__ b) {
    __shared__ float sW1[4], sb1[4], sW2[64], sb2[16], sW[1024], sb[64];
    int t = threadIdx.x;
    if (t < 4)  { sW1[t] = W1[t]; sb1[t] = b1[t]; }
    if (t < 64) { sW2[t] = W2[t]; sb[t] = b[t]; }
    if (t < 16) { sb2[t] = b2[t]; }
    for (int i = t; i < 1024; i += blockDim.x) sW[i] = W[i];
    __syncthreads();

    int m = blockIdx.x * blockDim.x + t;
    if (m >= M_NODES) return;

    float x = ev[m];

    float t4[4];
#pragma unroll
    for (int j = 0; j < 4; j++) t4[j] = elu1(fmaf(x, sW1[j], sb1[j]));

    float h16[16];
#pragma unroll
    for (int k = 0; k < 16; k++) {
        float v = sb2[k];
#pragma unroll
        for (int j = 0; j < 4; j++) v = fmaf(t4[j], sW2[j * 16 + k], v);
        h16[k] = v;
    }

    float4* q4 = reinterpret_cast<float4*>(g_qkv + (size_t)m * 64);
    float4* w4 = reinterpret_cast<float4*>(g_wV  + (size_t)m * 64);
#pragma unroll
    for (int c4 = 0; c4 < 16; c4++) {
        float o[4];
#pragma unroll
        for (int u = 0; u < 4; u++) {
            int c = c4 * 4 + u;
            float v = sb[c];
#pragma unroll
            for (int k = 0; k < 16; k++) v = fmaf(h16[k], sW[k * 64 + c], v);
            o[u] = v;
        }
        q4[c4] = make_float4(o[0], o[1], o[2], o[3]);
        w4[c4] = make_float4(0.f, 0.f, 0.f, 0.f);
    }
    reinterpret_cast<float4*>(g_Z)[m] = make_float4(0.f, 0.f, 0.f, 0.f);
}

// ---------------------------------------------------------------------------
// Kernel B: ONE thread per edge; loop over the 4 heads.
// e16/elu computed once per edge; Z accumulated as a single v4 RED.
// ---------------------------------------------------------------------------
__global__ __launch_bounds__(256)
void edge_kernel(const void* __restrict__ ei_raw,
                 const float* __restrict__ ef,
                 const float* __restrict__ W2, const float* __restrict__ b2,
                 const float* __restrict__ W,  const float* __restrict__ b) {
    __shared__ float sW2[64], sb2[16], sW[1024], sb[64];
    int t = threadIdx.x;
    if (t < 64) { sW2[t] = W2[t]; sb[t] = b[t]; }
    if (t < 16) { sb2[t] = b2[t]; }
    for (int i = t; i < 1024; i += blockDim.x) sW[i] = W[i];
    __syncthreads();

    int e = blockIdx.x * blockDim.x + t;
    if (e >= NE_EDGES) return;

    int src, dst;
    if (g_idx_is_64) {
        const long long* ei = (const long long*)ei_raw;
        src = (int)__ldg(ei + e);
        dst = (int)__ldg(ei + NE_EDGES + e);
    } else {
        const int* ei = (const int*)ei_raw;
        src = __ldg(ei + e);
        dst = __ldg(ei + NE_EDGES + e);
    }

    float4 f = __ldg(reinterpret_cast<const float4*>(ef) + e);
    float efv[4] = {f.x, f.y, f.z, f.w};

    // e16 = elu(edge_feature @ W2 + b2)   (once per edge)
    float e16[16];
#pragma unroll
    for (int k = 0; k < 16; k++) {
        float v = sb2[k];
#pragma unroll
        for (int j = 0; j < 4; j++) v = fmaf(efv[j], sW2[j * 16 + k], v);
        e16[k] = elu1(v);
    }

    const float4* srow = reinterpret_cast<const float4*>(g_qkv + (size_t)src * 64);
    const float4* drow = reinterpret_cast<const float4*>(g_qkv + (size_t)dst * 64);
    float*        wrow = g_wV + (size_t)dst * 64;

    float zacc[NHEADS];

#pragma unroll
    for (int head = 0; head < NHEADS; head++) {
        // gather this head's src/dst slices (64 B each)
        float4 s0 = __ldg(srow + head * 4 + 0);
        float4 s1 = __ldg(srow + head * 4 + 1);
        float4 s2 = __ldg(srow + head * 4 + 2);
        float4 s3 = __ldg(srow + head * 4 + 3);
        float4 q0 = __ldg(drow + head * 4 + 0);
        float4 q1 = __ldg(drow + head * 4 + 1);
        float4 q2 = __ldg(drow + head * 4 + 2);
        float4 q3 = __ldg(drow + head * 4 + 3);

        // p = s * q  (elementwise)
        float p[16] = {
            s0.x * q0.x, s0.y * q0.y, s0.z * q0.z, s0.w * q0.w,
            s1.x * q1.x, s1.y * q1.y, s1.z * q1.z, s1.w * q1.w,
            s2.x * q2.x, s2.y * q2.y, s2.z * q2.z, s2.w * q2.w,
            s3.x * q3.x, s3.y * q3.y, s3.z * q3.z, s3.w * q3.w };

        // score = sum_d p_d * (e16 @ W_head + b_head)_d
        const float* Wh = sW + head * 16;
        const float* bh = sb + head * 16;
        float sc = 0.f;
#pragma unroll
        for (int d = 0; d < 16; d++) {
            float v = bh[d];
#pragma unroll
            for (int k = 0; k < 16; k++) v = fmaf(e16[k], Wh[k * 64 + d], v);
            sc = fmaf(p[d], v, sc);
        }

        sc *= 0.25f;                                  // 1/sqrt(16)
        sc = fminf(fmaxf(sc, -5.0f), 5.0f);
        float w = __expf(sc);
        zacc[head] = w;

        float* dw = wrow + head * 16;
        red_add_v4(dw +  0, make_float4(s0.x * w, s0.y * w, s0.z * w, s0.w * w));
        red_add_v4(dw +  4, make_float4(s1.x * w, s1.y * w, s1.z * w, s1.w * w));
        red_add_v4(dw +  8, make_float4(s2.x * w, s2.y * w, s2.z * w, s2.w * w));
        red_add_v4(dw + 12, make_float4(s3.x * w, s3.y * w, s3.z * w, s3.w * w));
    }

    // all 4 heads' Z are contiguous: single v4 RED
    red_add_v4(g_Z + (size_t)dst * NHEADS,
               make_float4(zacc[0], zacc[1], zacc[2], zacc[3]));
}

// ---------------------------------------------------------------------------
// Kernel C: h = wV/(Z+1e-6); out = elu(h @ Wout + bout) @ Wout1 + bout1
// ---------------------------------------------------------------------------
__global__ __launch_bounds__(256)
void out_kernel(float* __restrict__ out,
                const float* __restrict__ Wout,  const float* __restrict__ bout,
                const float* __restrict__ Wout1, const float* __restrict__ bout1) {
    __shared__ float sWo[1024], sbo[16], sW1[16], sb1;
    int t = threadIdx.x;
    for (int i = t; i < 1024; i += blockDim.x) sWo[i] = Wout[i];
    if (t < 16) { sbo[t] = bout[t]; sW1[t] = Wout1[t]; }
    if (t == 0) sb1 = bout1[0];
    __syncthreads();

    int m = blockIdx.x * blockDim.x + t;
    if (m >= M_NODES) return;

    float4 zf = reinterpret_cast<const float4*>(g_Z)[m];
    float rz[4] = {1.0f / (zf.x + 1e-6f), 1.0f / (zf.y + 1e-6f),
                   1.0f / (zf.z + 1e-6f), 1.0f / (zf.w + 1e-6f)};

    float acc[16];
#pragma unroll
    for (int k = 0; k < 16; k++) acc[k] = sbo[k];

    const float4* wv4 = reinterpret_cast<const float4*>(g_wV + (size_t)m * 64);
#pragma unroll
    for (int c4 = 0; c4 < 16; c4++) {
        float4 v = wv4[c4];
        float r = rz[c4 >> 2];
        float hv[4] = {v.x * r, v.y * r, v.z * r, v.w * r};
#pragma unroll
        for (int u = 0; u < 4; u++) {
            int c = c4 * 4 + u;
#pragma unroll
            for (int k = 0; k < 16; k++) acc[k] = fmaf(hv[u], sWo[c * 16 + k], acc[k]);
        }
    }

    float val = sb1;
#pragma unroll
    for (int k = 0; k < 16; k++) {
        float a = elu1(acc[k]);
        val = fmaf(a, sW1[k], val);
    }
    out[m] = val;
}

// ---------------------------------------------------------------------------
extern "C" void kernel_launch(void* const* d_in, const int* in_sizes, int n_in,
                              void* d_out, int out_size) {
    // metadata order: node_attr, edge_index, edge_feature, edge_vector,
    //                 W1, b1, W2, b2, W, b, Wout, bout, Wout1, bout1
    const void*  ei   = d_in[1];
    const float* ef   = (const float*)d_in[2];
    const float* ev   = (const float*)d_in[3];
    const float* W1   = (const float*)d_in[4];
    const float* b1   = (const float*)d_in[5];
    const float* W2   = (const float*)d_in[6];
    const float* b2   = (const float*)d_in[7];
    const float* W    = (const float*)d_in[8];
    const float* b    = (const float*)d_in[9];
    const float* Wout = (const float*)d_in[10];
    const float* bout = (const float*)d_in[11];
    const float* Wout1= (const float*)d_in[12];
    const float* bout1= (const float*)d_in[13];
    float* out = (float*)d_out;

    probe_idx_kernel<<<1, 1>>>((const int*)ei);

    qkv_kernel<<<(M_NODES + 255) / 256, 256>>>(ev, W1, b1, W2, b2, W, b);

    edge_kernel<<<(NE_EDGES + 255) / 256, 256>>>(ei, ef, W2, b2, W, b);

    out_kernel<<<(M_NODES + 255) / 256, 256>>>(out, Wout, bout, Wout1, bout1);
}

// round 5
// speedup vs baseline: 3.0271x; 2.5103x over previous
#include <cuda_runtime.h>
#include <cstdint>

#define M_NODES 150000      // 3 * NATOMS
#define NE_EDGES 1500000
#define NHEADS 4
#define DHEAD 16

// Device-global scratch
__device__ float g_t4[M_NODES * 4];        // 2.4 MB: per-node low-rank features
__device__ float g_UZ[M_NODES * 20];       // 12 MB: [4 heads x 4 U] + [4 Z]
__device__ float g_A[256];                 // A[d*4+i] = (W2@W)[i,d]
__device__ float g_c[64];                  // c[d] = (b2@W + b)[d]
__device__ int   g_idx_is_64;

__device__ __forceinline__ float elu1(float v) {
    return v > 0.0f ? v : (__expf(v) - 1.0f);
}

__device__ __forceinline__ void red_add_v4(float* addr, float4 v) {
    asm volatile("red.global.add.v4.f32 [%0], {%1, %2, %3, %4};"
                 :: "l"(addr), "f"(v.x), "f"(v.y), "f"(v.z), "f"(v.w)
                 : "memory");
}

// ---------------------------------------------------------------------------
// Probe: int64 vs int32 edge_index
// ---------------------------------------------------------------------------
__global__ void probe_idx_kernel(const int* __restrict__ ei32) {
    int z = (ei32[1] == 0) & (ei32[3] == 0) & (ei32[5] == 0) & (ei32[7] == 0);
    g_idx_is_64 = z;
}

// ---------------------------------------------------------------------------
// Setup: A = W2 @ W  (4x64), c = b2 @ W + b  (64). One block, 256 threads.
// ---------------------------------------------------------------------------
__global__ void setup_kernel(const float* __restrict__ W2, const float* __restrict__ b2,
                             const float* __restrict__ W,  const float* __restrict__ b) {
    int t = threadIdx.x;           // t = d*4 + i
    int d = t >> 2, i = t & 3;
    float a = 0.f;
#pragma unroll
    for (int k = 0; k < 16; k++) a = fmaf(W2[i * 16 + k], W[k * 64 + d], a);
    g_A[t] = a;
    if (i == 0) {
        float cc = b[d];
#pragma unroll
        for (int k = 0; k < 16; k++) cc = fmaf(b2[k], W[k * 64 + d], cc);
        g_c[d] = cc;
    }
}

// ---------------------------------------------------------------------------
// Kernel A: t4[m] = elu(x*W1 + b1); zero the UZ accumulator row.
// ---------------------------------------------------------------------------
__global__ __launch_bounds__(256)
void t4_kernel(const float* __restrict__ ev,
               const float* __restrict__ W1, const float* __restrict__ b1) {
    __shared__ float sW1[4], sb1[4];
    int t = threadIdx.x;
    if (t < 4) { sW1[t] = W1[t]; sb1[t] = b1[t]; }
    __syncthreads();

    int m = blockIdx.x * blockDim.x + t;
    if (m >= M_NODES) return;

    float x = ev[m];
    float4 t4;
    t4.x = elu1(fmaf(x, sW1[0], sb1[0]));
    t4.y = elu1(fmaf(x, sW1[1], sb1[1]));
    t4.z = elu1(fmaf(x, sW1[2], sb1[2]));
    t4.w = elu1(fmaf(x, sW1[3], sb1[3]));
    reinterpret_cast<float4*>(g_t4)[m] = t4;

    float4 z4 = make_float4(0.f, 0.f, 0.f, 0.f);
    float4* uz = reinterpret_cast<float4*>(g_UZ + (size_t)m * 20);
#pragma unroll
    for (int k = 0; k < 5; k++) uz[k] = z4;
}

// ---------------------------------------------------------------------------
// Kernel B: one thread per edge.
//   e16 = elu(ef@W2+b2)
//   for d: E_d = e16.W[:,d]+b_d ; q_d = tq.A[:,d]+c_d ; r = E_d*q_d
//          v[h][i] += A[i,d]*r (i<4) ; v[h][4] += c_d*r
//   score_h = (sum_i ts_i v[h][i] + v[h][4]) * 0.25 -> clip -> exp -> w
//   RED: U[dst,h,:] += w*ts ; Z[dst,h] += w        (5 x red.v4 total)
// ---------------------------------------------------------------------------
__global__ __launch_bounds__(256)
void edge_kernel(const void* __restrict__ ei_raw,
                 const float* __restrict__ ef,
                 const float* __restrict__ W2, const float* __restrict__ b2,
                 const float* __restrict__ W,  const float* __restrict__ b) {
    __shared__ float sW2[64], sb2[16], sW[1024], sb[64], sA[256], sc_[64];
    int t = threadIdx.x;
    if (t < 64) { sW2[t] = W2[t]; sb[t] = b[t]; sc_[t] = g_c[t]; }
    if (t < 16) { sb2[t] = b2[t]; }
    for (int i = t; i < 1024; i += blockDim.x) sW[i] = W[i];
    if (t < 256) sA[t] = g_A[t];
    __syncthreads();

    int e = blockIdx.x * blockDim.x + t;
    if (e >= NE_EDGES) return;

    int src, dst;
    if (g_idx_is_64) {
        const long long* ei = (const long long*)ei_raw;
        src = (int)__ldg(ei + e);
        dst = (int)__ldg(ei + NE_EDGES + e);
    } else {
        const int* ei = (const int*)ei_raw;
        src = __ldg(ei + e);
        dst = __ldg(ei + NE_EDGES + e);
    }

    // low-rank node features (16 B gathers from a 2.4 MB table)
    float4 tsv = __ldg(reinterpret_cast<const float4*>(g_t4) + src);
    float4 tqv = __ldg(reinterpret_cast<const float4*>(g_t4) + dst);
    float ts[4] = {tsv.x, tsv.y, tsv.z, tsv.w};
    float tq[4] = {tqv.x, tqv.y, tqv.z, tqv.w};

    float4 f = __ldg(reinterpret_cast<const float4*>(ef) + e);
    float efv[4] = {f.x, f.y, f.z, f.w};

    // e16 = elu(edge_feature @ W2 + b2)
    float e16[16];
#pragma unroll
    for (int k = 0; k < 16; k++) {
        float v = sb2[k];
#pragma unroll
        for (int j = 0; j < 4; j++) v = fmaf(efv[j], sW2[j * 16 + k], v);
        e16[k] = elu1(v);
    }

    float v[NHEADS][5];
#pragma unroll
    for (int h = 0; h < NHEADS; h++)
#pragma unroll
        for (int i = 0; i < 5; i++) v[h][i] = 0.f;

#pragma unroll
    for (int h = 0; h < NHEADS; h++) {
#pragma unroll
        for (int dd = 0; dd < 16; dd++) {
            int d = h * 16 + dd;
            // E_d = e16 . W[:,d] + b_d   (uniform smem reads -> broadcast)
            float E = sb[d];
#pragma unroll
            for (int k = 0; k < 16; k++) E = fmaf(e16[k], sW[k * 64 + d], E);
            // q_d = tq . A[:,d] + c_d
            float q = sc_[d];
#pragma unroll
            for (int i = 0; i < 4; i++) q = fmaf(tq[i], sA[d * 4 + i], q);
            float r = E * q;
#pragma unroll
            for (int i = 0; i < 4; i++) v[h][i] = fmaf(sA[d * 4 + i], r, v[h][i]);
            v[h][4] = fmaf(sc_[d], r, v[h][4]);      // constant term carries c_d
        }
    }

    float* uz = g_UZ + (size_t)dst * 20;
    float zacc[NHEADS];
#pragma unroll
    for (int h = 0; h < NHEADS; h++) {
        float sc = v[h][4];
#pragma unroll
        for (int i = 0; i < 4; i++) sc = fmaf(ts[i], v[h][i], sc);
        sc *= 0.25f;                                  // 1/sqrt(16)
        sc = fminf(fmaxf(sc, -5.0f), 5.0f);
        float w = __expf(sc);
        zacc[h] = w;
        red_add_v4(uz + h * 4, make_float4(ts[0] * w, ts[1] * w, ts[2] * w, ts[3] * w));
    }
    red_add_v4(uz + 16, make_float4(zacc[0], zacc[1], zacc[2], zacc[3]));
}

// ---------------------------------------------------------------------------
// Kernel C: wV_d = A[:,d].U_h + c_d*Z_h ; h_d = wV_d/(Z_h+1e-6);
//           out = elu(h @ Wout + bout) @ Wout1 + bout1
// ---------------------------------------------------------------------------
__global__ __launch_bounds__(256)
void out_kernel(float* __restrict__ out,
                const float* __restrict__ Wout,  const float* __restrict__ bout,
                const float* __restrict__ Wout1, const float* __restrict__ bout1) {
    __shared__ float sWo[1024], sbo[16], sW1[16], sb1, sA[256], sc_[64];
    int t = threadIdx.x;
    for (int i = t; i < 1024; i += blockDim.x) sWo[i] = Wout[i];
    if (t < 16) { sbo[t] = bout[t]; sW1[t] = Wout1[t]; }
    if (t == 0) sb1 = bout1[0];
    if (t < 256) sA[t] = g_A[t];
    if (t < 64)  sc_[t] = g_c[t];
    __syncthreads();

    int m = blockIdx.x * blockDim.x + t;
    if (m >= M_NODES) return;

    const float4* uz4 = reinterpret_cast<const float4*>(g_UZ + (size_t)m * 20);
    float4 U0 = uz4[0], U1 = uz4[1], U2 = uz4[2], U3 = uz4[3], Zv = uz4[4];
    float U[NHEADS][4] = {
        {U0.x, U0.y, U0.z, U0.w}, {U1.x, U1.y, U1.z, U1.w},
        {U2.x, U2.y, U2.z, U2.w}, {U3.x, U3.y, U3.z, U3.w}};
    float Z[NHEADS] = {Zv.x, Zv.y, Zv.z, Zv.w};

    float acc[16];
#pragma unroll
    for (int k = 0; k < 16; k++) acc[k] = sbo[k];

#pragma unroll
    for (int h = 0; h < NHEADS; h++) {
        float rz = 1.0f / (Z[h] + 1e-6f);
#pragma unroll
        for (int dd = 0; dd < 16; dd++) {
            int d = h * 16 + dd;
            float wv = sc_[d] * Z[h];
#pragma unroll
            for (int i = 0; i < 4; i++) wv = fmaf(sA[d * 4 + i], U[h][i], wv);
            float hv = wv * rz;
#pragma unroll
            for (int k = 0; k < 16; k++) acc[k] = fmaf(hv, sWo[d * 16 + k], acc[k]);
        }
    }

    float val = sb1;
#pragma unroll
    for (int k = 0; k < 16; k++) {
        float a = elu1(acc[k]);
        val = fmaf(a, sW1[k], val);
    }
    out[m] = val;
}

// ---------------------------------------------------------------------------
extern "C" void kernel_launch(void* const* d_in, const int* in_sizes, int n_in,
                              void* d_out, int out_size) {
    // order: node_attr, edge_index, edge_feature, edge_vector,
    //        W1, b1, W2, b2, W, b, Wout, bout, Wout1, bout1
    const void*  ei   = d_in[1];
    const float* ef   = (const float*)d_in[2];
    const float* ev   = (const float*)d_in[3];
    const float* W1   = (const float*)d_in[4];
    const float* b1   = (const float*)d_in[5];
    const float* W2   = (const float*)d_in[6];
    const float* b2   = (const float*)d_in[7];
    const float* W    = (const float*)d_in[8];
    const float* b    = (const float*)d_in[9];
    const float* Wout = (const float*)d_in[10];
    const float* bout = (const float*)d_in[11];
    const float* Wout1= (const float*)d_in[12];
    const float* bout1= (const float*)d_in[13];
    float* out = (float*)d_out;

    probe_idx_kernel<<<1, 1>>>((const int*)ei);
    setup_kernel<<<1, 256>>>(W2, b2, W, b);
    t4_kernel<<<(M_NODES + 255) / 256, 256>>>(ev, W1, b1);
    edge_kernel<<<(NE_EDGES + 255) / 256, 256>>>(ei, ef, W2, b2, W, b);
    out_kernel<<<(M_NODES + 255) / 256, 256>>>(out, Wout, bout, Wout1, bout1);
}

// round 6
// speedup vs baseline: 3.1409x; 1.0376x over previous
#include <cuda_runtime.h>
#include <cstdint>

#define M_NODES 150000      // 3 * NATOMS
#define NE_EDGES 1500000
#define NHEADS 4
#define DHEAD 16

typedef unsigned long long ull;

// Device-global scratch
__device__ float  g_t4[M_NODES * 4];       // per-node low-rank features
__device__ float  g_UZ[M_NODES * 20];      // [4 heads x 4 U] + [4 Z]
__device__ float  g_A[256];                // A[d*4+i] = (W2@W)[i,d]
__device__ float  g_c[64];                 // c[d] = (b2@W + b)[d]
// packed-by-d-pair tables (dp = d/2, 32 pairs)
__device__ float2 g_Wp[32 * 16];           // Wp[dp*16+k] = (W[k,2dp], W[k,2dp+1])
__device__ float2 g_Ap[4 * 32];            // Ap[i*32+dp] = (A[i,2dp], A[i,2dp+1])
__device__ float2 g_bp[32];                // (b[2dp], b[2dp+1])
__device__ float2 g_cp[32];                // (c[2dp], c[2dp+1])
__device__ int    g_idx_is_64;

__device__ __forceinline__ float elu1(float v) {
    return v > 0.0f ? v : (__expf(v) - 1.0f);
}

__device__ __forceinline__ void red_add_v4(float* addr, float4 v) {
    asm volatile("red.global.add.v4.f32 [%0], {%1, %2, %3, %4};"
                 :: "l"(addr), "f"(v.x), "f"(v.y), "f"(v.z), "f"(v.w)
                 : "memory");
}

// packed f32x2 helpers (Blackwell): FFMA2 via PTX only
__device__ __forceinline__ ull pk2(float lo, float hi) {
    ull r; asm("mov.b64 %0, {%1, %2};" : "=l"(r) : "f"(lo), "f"(hi)); return r;
}
__device__ __forceinline__ void upk2(float& lo, float& hi, ull v) {
    asm("mov.b64 {%0, %1}, %2;" : "=f"(lo), "=f"(hi) : "l"(v));
}
__device__ __forceinline__ void fma2(ull& d, ull a, ull b) {   // d = a*b + d
    asm("fma.rn.f32x2 %0, %1, %2, %0;" : "+l"(d) : "l"(a), "l"(b));
}
__device__ __forceinline__ ull mul2(ull a, ull b) {
    ull r; asm("mul.rn.f32x2 %0, %1, %2;" : "=l"(r) : "l"(a), "l"(b)); return r;
}

// ---------------------------------------------------------------------------
__global__ void probe_idx_kernel(const int* __restrict__ ei32) {
    int z = (ei32[1] == 0) & (ei32[3] == 0) & (ei32[5] == 0) & (ei32[7] == 0);
    g_idx_is_64 = z;
}

// ---------------------------------------------------------------------------
// Setup: A = W2@W, c = b2@W + b, plus d-pair-packed tables. One block of 256.
// ---------------------------------------------------------------------------
__global__ void setup_kernel(const float* __restrict__ W2, const float* __restrict__ b2,
                             const float* __restrict__ W,  const float* __restrict__ b) {
    __shared__ float shA[256], shc[64];
    int t = threadIdx.x;           // t = d*4 + i
    int d = t >> 2, i = t & 3;
    float a = 0.f;
#pragma unroll
    for (int k = 0; k < 16; k++) a = fmaf(W2[i * 16 + k], W[k * 64 + d], a);
    shA[t] = a;
    if (i == 0) {
        float cc = b[d];
#pragma unroll
        for (int k = 0; k < 16; k++) cc = fmaf(b2[k], W[k * 64 + d], cc);
        shc[d] = cc;
    }
    __syncthreads();

    g_A[t] = shA[t];
    if (t < 64) g_c[t] = shc[t];

    if (t < 32) {                  // dp = t
        int dp = t;
        g_bp[dp] = make_float2(b[2 * dp], b[2 * dp + 1]);
        g_cp[dp] = make_float2(shc[2 * dp], shc[2 * dp + 1]);
#pragma unroll
        for (int k = 0; k < 16; k++)
            g_Wp[dp * 16 + k] = make_float2(W[k * 64 + 2 * dp], W[k * 64 + 2 * dp + 1]);
#pragma unroll
        for (int i2 = 0; i2 < 4; i2++)
            g_Ap[i2 * 32 + dp] = make_float2(shA[(2 * dp) * 4 + i2], shA[(2 * dp + 1) * 4 + i2]);
    }
}

// ---------------------------------------------------------------------------
// Kernel A: t4[m] = elu(x*W1 + b1); zero the UZ accumulator row.
// ---------------------------------------------------------------------------
__global__ __launch_bounds__(256)
void t4_kernel(const float* __restrict__ ev,
               const float* __restrict__ W1, const float* __restrict__ b1) {
    __shared__ float sW1[4], sb1[4];
    int t = threadIdx.x;
    if (t < 4) { sW1[t] = W1[t]; sb1[t] = b1[t]; }
    __syncthreads();

    int m = blockIdx.x * blockDim.x + t;
    if (m >= M_NODES) return;

    float x = ev[m];
    float4 t4;
    t4.x = elu1(fmaf(x, sW1[0], sb1[0]));
    t4.y = elu1(fmaf(x, sW1[1], sb1[1]));
    t4.z = elu1(fmaf(x, sW1[2], sb1[2]));
    t4.w = elu1(fmaf(x, sW1[3], sb1[3]));
    reinterpret_cast<float4*>(g_t4)[m] = t4;

    float4 z4 = make_float4(0.f, 0.f, 0.f, 0.f);
    float4* uz = reinterpret_cast<float4*>(g_UZ + (size_t)m * 20);
#pragma unroll
    for (int k = 0; k < 5; k++) uz[k] = z4;
}

// ---------------------------------------------------------------------------
// Kernel B: one thread per edge, d processed in packed pairs with fma.f32x2.
// ---------------------------------------------------------------------------
__global__ __launch_bounds__(256, 2)
void edge_kernel(const void* __restrict__ ei_raw,
                 const float* __restrict__ ef,
                 const float* __restrict__ W2, const float* __restrict__ b2) {
    __shared__ ull  sWp[512];          // [dp][k] packed pairs (4 KB)
    __shared__ ull  sAp[128];          // [i][dp] packed pairs (1 KB)
    __shared__ ull  sbp[32], scp[32];
    __shared__ float sW2[64], sb2[16];

    int t = threadIdx.x;
    {
        const ull* wp = (const ull*)g_Wp;
        sWp[t]       = wp[t];
        sWp[t + 256] = wp[t + 256];
        if (t < 128) sAp[t] = ((const ull*)g_Ap)[t];
        if (t < 32)  { sbp[t] = ((const ull*)g_bp)[t]; scp[t] = ((const ull*)g_cp)[t]; }
        if (t < 64)  sW2[t] = W2[t];
        if (t < 16)  sb2[t] = b2[t];
    }
    __syncthreads();

    int e = blockIdx.x * blockDim.x + t;
    if (e >= NE_EDGES) return;

    int src, dst;
    if (g_idx_is_64) {
        const long long* ei = (const long long*)ei_raw;
        src = (int)__ldg(ei + e);
        dst = (int)__ldg(ei + NE_EDGES + e);
    } else {
        const int* ei = (const int*)ei_raw;
        src = __ldg(ei + e);
        dst = __ldg(ei + NE_EDGES + e);
    }

    float4 tsv = __ldg(reinterpret_cast<const float4*>(g_t4) + src);
    float4 tqv = __ldg(reinterpret_cast<const float4*>(g_t4) + dst);

    float4 f = __ldg(reinterpret_cast<const float4*>(ef) + e);
    float efv[4] = {f.x, f.y, f.z, f.w};

    // e16 = elu(edge_feature @ W2 + b2), pre-dup'd into f32x2 broadcast pairs
    ull e2[16];
#pragma unroll
    for (int k = 0; k < 16; k++) {
        float v = sb2[k];
#pragma unroll
        for (int j = 0; j < 4; j++) v = fmaf(efv[j], sW2[j * 16 + k], v);
        v = elu1(v);
        e2[k] = pk2(v, v);
    }

    ull tq2[4] = {pk2(tqv.x, tqv.x), pk2(tqv.y, tqv.y),
                  pk2(tqv.z, tqv.z), pk2(tqv.w, tqv.w)};
    float ts[4] = {tsv.x, tsv.y, tsv.z, tsv.w};

    float* uz = g_UZ + (size_t)dst * 20;
    float zacc[NHEADS];

#pragma unroll
    for (int h = 0; h < NHEADS; h++) {
        ull V0 = 0, V1 = 0, V2a = 0, V3 = 0, Vc = 0;
#pragma unroll
        for (int dpo = 0; dpo < 8; dpo++) {
            int dp = h * 8 + dpo;
            // E pair = b_pair + sum_k e16_k * W[k, dpair]
            ull E2 = sbp[dp];
            const ulonglong2* wp2 = reinterpret_cast<const ulonglong2*>(sWp) + dp * 8;
#pragma unroll
            for (int kk = 0; kk < 8; kk++) {
                ulonglong2 ww = wp2[kk];
                fma2(E2, e2[2 * kk],     ww.x);
                fma2(E2, e2[2 * kk + 1], ww.y);
            }
            // q pair = c_pair + sum_i tq_i * A[i, dpair]
            ull a0 = sAp[0 * 32 + dp], a1 = sAp[1 * 32 + dp];
            ull a2 = sAp[2 * 32 + dp], a3 = sAp[3 * 32 + dp];
            ull cU = scp[dp];
            ull Q2 = cU;
            fma2(Q2, tq2[0], a0); fma2(Q2, tq2[1], a1);
            fma2(Q2, tq2[2], a2); fma2(Q2, tq2[3], a3);

            ull R2 = mul2(E2, Q2);
            fma2(V0, R2, a0); fma2(V1, R2, a1);
            fma2(V2a, R2, a2); fma2(V3, R2, a3);
            fma2(Vc, R2, cU);
        }
        // reduce packed accumulators
        float l, hst, v0, v1, v2, v3, vc;
        upk2(l, hst, V0);  v0 = l + hst;
        upk2(l, hst, V1);  v1 = l + hst;
        upk2(l, hst, V2a); v2 = l + hst;
        upk2(l, hst, V3);  v3 = l + hst;
        upk2(l, hst, Vc);  vc = l + hst;

        float sc = vc;
        sc = fmaf(ts[0], v0, sc); sc = fmaf(ts[1], v1, sc);
        sc = fmaf(ts[2], v2, sc); sc = fmaf(ts[3], v3, sc);
        sc *= 0.25f;                                  // 1/sqrt(16)
        sc = fminf(fmaxf(sc, -5.0f), 5.0f);
        float w = __expf(sc);
        zacc[h] = w;
        red_add_v4(uz + h * 4, make_float4(ts[0] * w, ts[1] * w, ts[2] * w, ts[3] * w));
    }
    red_add_v4(uz + 16, make_float4(zacc[0], zacc[1], zacc[2], zacc[3]));
}

// ---------------------------------------------------------------------------
// Kernel C: wV_d = A[:,d].U_h + c_d*Z_h ; h_d = wV_d/(Z_h+1e-6);
//           out = elu(h @ Wout + bout) @ Wout1 + bout1
// ---------------------------------------------------------------------------
__global__ __launch_bounds__(256)
void out_kernel(float* __restrict__ out,
                const float* __restrict__ Wout,  const float* __restrict__ bout,
                const float* __restrict__ Wout1, const float* __restrict__ bout1) {
    __shared__ float sWo[1024], sbo[16], sW1[16], sb1, sA[256], sc_[64];
    int t = threadIdx.x;
    for (int i = t; i < 1024; i += blockDim.x) sWo[i] = Wout[i];
    if (t < 16) { sbo[t] = bout[t]; sW1[t] = Wout1[t]; }
    if (t == 0) sb1 = bout1[0];
    if (t < 256) sA[t] = g_A[t];
    if (t < 64)  sc_[t] = g_c[t];
    __syncthreads();

    int m = blockIdx.x * blockDim.x + t;
    if (m >= M_NODES) return;

    const float4* uz4 = reinterpret_cast<const float4*>(g_UZ + (size_t)m * 20);
    float4 U0 = uz4[0], U1 = uz4[1], U2 = uz4[2], U3 = uz4[3], Zv = uz4[4];
    float U[NHEADS][4] = {
        {U0.x, U0.y, U0.z, U0.w}, {U1.x, U1.y, U1.z, U1.w},
        {U2.x, U2.y, U2.z, U2.w}, {U3.x, U3.y, U3.z, U3.w}};
    float Z[NHEADS] = {Zv.x, Zv.y, Zv.z, Zv.w};

    float acc[16];
#pragma unroll
    for (int k = 0; k < 16; k++) acc[k] = sbo[k];

#pragma unroll
    for (int h = 0; h < NHEADS; h++) {
        float rz = 1.0f / (Z[h] + 1e-6f);
#pragma unroll
        for (int dd = 0; dd < 16; dd++) {
            int d = h * 16 + dd;
            float wv = sc_[d] * Z[h];
#pragma unroll
            for (int i = 0; i < 4; i++) wv = fmaf(sA[d * 4 + i], U[h][i], wv);
            float hv = wv * rz;
#pragma unroll
            for (int k = 0; k < 16; k++) acc[k] = fmaf(hv, sWo[d * 16 + k], acc[k]);
        }
    }

    float val = sb1;
#pragma unroll
    for (int k = 0; k < 16; k++) {
        float a = elu1(acc[k]);
        val = fmaf(a, sW1[k], val);
    }
    out[m] = val;
}

// ---------------------------------------------------------------------------
extern "C" void kernel_launch(void* const* d_in, const int* in_sizes, int n_in,
                              void* d_out, int out_size) {
    // order: node_attr, edge_index, edge_feature, edge_vector,
    //        W1, b1, W2, b2, W, b, Wout, bout, Wout1, bout1
    const void*  ei   = d_in[1];
    const float* ef   = (const float*)d_in[2];
    const float* ev   = (const float*)d_in[3];
    const float* W1   = (const float*)d_in[4];
    const float* b1   = (const float*)d_in[5];
    const float* W2   = (const float*)d_in[6];
    const float* b2   = (const float*)d_in[7];
    const float* W    = (const float*)d_in[8];
    const float* b    = (const float*)d_in[9];
    const float* Wout = (const float*)d_in[10];
    const float* bout = (const float*)d_in[11];
    const float* Wout1= (const float*)d_in[12];
    const float* bout1= (const float*)d_in[13];
    float* out = (float*)d_out;

    probe_idx_kernel<<<1, 1>>>((const int*)ei);
    setup_kernel<<<1, 256>>>(W2, b2, W, b);
    t4_kernel<<<(M_NODES + 255) / 256, 256>>>(ev, W1, b1);
    edge_kernel<<<(NE_EDGES + 255) / 256, 256>>>(ei, ef, W2, b2);
    out_kernel<<<(M_NODES + 255) / 256, 256>>>(out, Wout, bout, Wout1, bout1);
}

// round 7
// speedup vs baseline: 3.8070x; 1.2121x over previous
#include <cuda_runtime.h>
#include <cstdint>

#define M_NODES 150000      // 3 * NATOMS
#define NE_EDGES 1500000
#define NE_HALF  750000
#define NHEADS 4
#define DHEAD 16

typedef unsigned long long ull;

// Device-global scratch
__device__ float  g_t4[M_NODES * 4];       // per-node low-rank features
__device__ float  g_UZ[M_NODES * 20];      // [4 heads x 4 U] + [4 Z]
__device__ float  g_A[256];                // A[d*4+i] = (W2@W)[i,d]
__device__ float  g_c[64];                 // c[d] = (b2@W + b)[d]
// packed-by-d-pair tables (dp = d/2, 32 pairs)
__device__ float2 g_Wp[32 * 16];           // Wp[dp*16+k] = (W[k,2dp], W[k,2dp+1])
__device__ float2 g_Ap[4 * 32];            // Ap[i*32+dp] = (A[i,2dp], A[i,2dp+1])
__device__ float2 g_bp[32];                // (b[2dp], b[2dp+1])
__device__ float2 g_cp[32];                // (c[2dp], c[2dp+1])
__device__ int    g_idx_is_64;

__device__ __forceinline__ float elu1(float v) {
    return v > 0.0f ? v : (__expf(v) - 1.0f);
}

__device__ __forceinline__ void red_add_v4(float* addr, float4 v) {
    asm volatile("red.global.add.v4.f32 [%0], {%1, %2, %3, %4};"
                 :: "l"(addr), "f"(v.x), "f"(v.y), "f"(v.z), "f"(v.w)
                 : "memory");
}

// packed f32x2 helpers (Blackwell): FFMA2 via PTX only
__device__ __forceinline__ ull pk2(float lo, float hi) {
    ull r; asm("mov.b64 %0, {%1, %2};" : "=l"(r) : "f"(lo), "f"(hi)); return r;
}
__device__ __forceinline__ void upk2(float& lo, float& hi, ull v) {
    asm("mov.b64 {%0, %1}, %2;" : "=f"(lo), "=f"(hi) : "l"(v));
}
__device__ __forceinline__ void fma2(ull& d, ull a, ull b) {   // d = a*b + d
    asm("fma.rn.f32x2 %0, %1, %2, %0;" : "+l"(d) : "l"(a), "l"(b));
}
__device__ __forceinline__ ull mul2(ull a, ull b) {
    ull r; asm("mul.rn.f32x2 %0, %1, %2;" : "=l"(r) : "l"(a), "l"(b)); return r;
}

// ---------------------------------------------------------------------------
__global__ void probe_idx_kernel(const int* __restrict__ ei32) {
    int z = (ei32[1] == 0) & (ei32[3] == 0) & (ei32[5] == 0) & (ei32[7] == 0);
    g_idx_is_64 = z;
}

// ---------------------------------------------------------------------------
// Setup: A = W2@W, c = b2@W + b, plus d-pair-packed tables. One block of 256.
// ---------------------------------------------------------------------------
__global__ void setup_kernel(const float* __restrict__ W2, const float* __restrict__ b2,
                             const float* __restrict__ W,  const float* __restrict__ b) {
    __shared__ float shA[256], shc[64];
    int t = threadIdx.x;           // t = d*4 + i
    int d = t >> 2, i = t & 3;
    float a = 0.f;
#pragma unroll
    for (int k = 0; k < 16; k++) a = fmaf(W2[i * 16 + k], W[k * 64 + d], a);
    shA[t] = a;
    if (i == 0) {
        float cc = b[d];
#pragma unroll
        for (int k = 0; k < 16; k++) cc = fmaf(b2[k], W[k * 64 + d], cc);
        shc[d] = cc;
    }
    __syncthreads();

    g_A[t] = shA[t];
    if (t < 64) g_c[t] = shc[t];

    if (t < 32) {                  // dp = t
        int dp = t;
        g_bp[dp] = make_float2(b[2 * dp], b[2 * dp + 1]);
        g_cp[dp] = make_float2(shc[2 * dp], shc[2 * dp + 1]);
#pragma unroll
        for (int k = 0; k < 16; k++)
            g_Wp[dp * 16 + k] = make_float2(W[k * 64 + 2 * dp], W[k * 64 + 2 * dp + 1]);
#pragma unroll
        for (int i2 = 0; i2 < 4; i2++)
            g_Ap[i2 * 32 + dp] = make_float2(shA[(2 * dp) * 4 + i2], shA[(2 * dp + 1) * 4 + i2]);
    }
}

// ---------------------------------------------------------------------------
// Kernel A: t4[m] = elu(x*W1 + b1); zero the UZ accumulator row.
// ---------------------------------------------------------------------------
__global__ __launch_bounds__(256)
void t4_kernel(const float* __restrict__ ev,
               const float* __restrict__ W1, const float* __restrict__ b1) {
    __shared__ float sW1[4], sb1[4];
    int t = threadIdx.x;
    if (t < 4) { sW1[t] = W1[t]; sb1[t] = b1[t]; }
    __syncthreads();

    int m = blockIdx.x * blockDim.x + t;
    if (m >= M_NODES) return;

    float x = ev[m];
    float4 t4;
    t4.x = elu1(fmaf(x, sW1[0], sb1[0]));
    t4.y = elu1(fmaf(x, sW1[1], sb1[1]));
    t4.z = elu1(fmaf(x, sW1[2], sb1[2]));
    t4.w = elu1(fmaf(x, sW1[3], sb1[3]));
    reinterpret_cast<float4*>(g_t4)[m] = t4;

    float4 z4 = make_float4(0.f, 0.f, 0.f, 0.f);
    float4* uz = reinterpret_cast<float4*>(g_UZ + (size_t)m * 20);
#pragma unroll
    for (int k = 0; k < 5; k++) uz[k] = z4;
}

// ---------------------------------------------------------------------------
// Kernel B: TWO edges per thread (e and e+NE/2). Every shared-memory weight
// load is amortized across both edges' packed-f32x2 FMA chains.
// ---------------------------------------------------------------------------
__global__ __launch_bounds__(128)
void edge_kernel(const void* __restrict__ ei_raw,
                 const float* __restrict__ ef,
                 const float* __restrict__ W2, const float* __restrict__ b2) {
    __shared__ ull  sWp[512];          // [dp][k] packed pairs (4 KB)
    __shared__ ull  sAp[128];          // [i][dp] packed pairs (1 KB)
    __shared__ ull  sbp[32], scp[32];
    __shared__ float sW2[64], sb2[16];

    int t = threadIdx.x;
    {
        const ull* wp = (const ull*)g_Wp;
#pragma unroll
        for (int i = 0; i < 4; i++) sWp[t + 128 * i] = wp[t + 128 * i];
        if (t < 128) sAp[t] = ((const ull*)g_Ap)[t];
        if (t < 32)  { sbp[t] = ((const ull*)g_bp)[t]; scp[t] = ((const ull*)g_cp)[t]; }
        if (t < 64)  sW2[t] = W2[t];
        if (t < 16)  sb2[t] = b2[t];
    }
    __syncthreads();

    int ea = blockIdx.x * blockDim.x + t;
    if (ea >= NE_HALF) return;
    int eb = ea + NE_HALF;

    int srcA, dstA, srcB, dstB;
    if (g_idx_is_64) {
        const long long* ei = (const long long*)ei_raw;
        srcA = (int)__ldg(ei + ea);
        dstA = (int)__ldg(ei + NE_EDGES + ea);
        srcB = (int)__ldg(ei + eb);
        dstB = (int)__ldg(ei + NE_EDGES + eb);
    } else {
        const int* ei = (const int*)ei_raw;
        srcA = __ldg(ei + ea);
        dstA = __ldg(ei + NE_EDGES + ea);
        srcB = __ldg(ei + eb);
        dstB = __ldg(ei + NE_EDGES + eb);
    }

    // front-batch all gathers (MLP)
    float4 tsvA = __ldg(reinterpret_cast<const float4*>(g_t4) + srcA);
    float4 tqvA = __ldg(reinterpret_cast<const float4*>(g_t4) + dstA);
    float4 tsvB = __ldg(reinterpret_cast<const float4*>(g_t4) + srcB);
    float4 tqvB = __ldg(reinterpret_cast<const float4*>(g_t4) + dstB);
    float4 fA = __ldg(reinterpret_cast<const float4*>(ef) + ea);
    float4 fB = __ldg(reinterpret_cast<const float4*>(ef) + eb);

    float efA[4] = {fA.x, fA.y, fA.z, fA.w};
    float efB[4] = {fB.x, fB.y, fB.z, fB.w};

    // e16 for both edges, sharing W2 reads; dup-packed pairs
    ull e2a[16], e2b[16];
#pragma unroll
    for (int k = 0; k < 16; k++) {
        float w0 = sW2[0 * 16 + k], w1 = sW2[1 * 16 + k];
        float w2 = sW2[2 * 16 + k], w3 = sW2[3 * 16 + k];
        float bb = sb2[k];
        float va = bb, vb = bb;
        va = fmaf(efA[0], w0, va); vb = fmaf(efB[0], w0, vb);
        va = fmaf(efA[1], w1, va); vb = fmaf(efB[1], w1, vb);
        va = fmaf(efA[2], w2, va); vb = fmaf(efB[2], w2, vb);
        va = fmaf(efA[3], w3, va); vb = fmaf(efB[3], w3, vb);
        va = elu1(va); vb = elu1(vb);
        e2a[k] = pk2(va, va);
        e2b[k] = pk2(vb, vb);
    }

    ull tq2a[4] = {pk2(tqvA.x, tqvA.x), pk2(tqvA.y, tqvA.y),
                   pk2(tqvA.z, tqvA.z), pk2(tqvA.w, tqvA.w)};
    ull tq2b[4] = {pk2(tqvB.x, tqvB.x), pk2(tqvB.y, tqvB.y),
                   pk2(tqvB.z, tqvB.z), pk2(tqvB.w, tqvB.w)};
    float tsA[4] = {tsvA.x, tsvA.y, tsvA.z, tsvA.w};
    float tsB[4] = {tsvB.x, tsvB.y, tsvB.z, tsvB.w};

    float* uzA = g_UZ + (size_t)dstA * 20;
    float* uzB = g_UZ + (size_t)dstB * 20;
    float zaccA[NHEADS], zaccB[NHEADS];

#pragma unroll
    for (int h = 0; h < NHEADS; h++) {
        ull VA0 = 0, VA1 = 0, VA2 = 0, VA3 = 0, VAc = 0;
        ull VB0 = 0, VB1 = 0, VB2 = 0, VB3 = 0, VBc = 0;
#pragma unroll
        for (int dpo = 0; dpo < 8; dpo++) {
            int dp = h * 8 + dpo;
            ull bU = sbp[dp];
            ull E2a = bU, E2b = bU;
            const ulonglong2* wp2 = reinterpret_cast<const ulonglong2*>(sWp) + dp * 8;
#pragma unroll
            for (int kk = 0; kk < 8; kk++) {
                ulonglong2 ww = wp2[kk];
                fma2(E2a, e2a[2 * kk],     ww.x);
                fma2(E2b, e2b[2 * kk],     ww.x);
                fma2(E2a, e2a[2 * kk + 1], ww.y);
                fma2(E2b, e2b[2 * kk + 1], ww.y);
            }
            ull a0 = sAp[0 * 32 + dp], a1 = sAp[1 * 32 + dp];
            ull a2 = sAp[2 * 32 + dp], a3 = sAp[3 * 32 + dp];
            ull cU = scp[dp];

            ull Q2a = cU, Q2b = cU;
            fma2(Q2a, tq2a[0], a0); fma2(Q2b, tq2b[0], a0);
            fma2(Q2a, tq2a[1], a1); fma2(Q2b, tq2b[1], a1);
            fma2(Q2a, tq2a[2], a2); fma2(Q2b, tq2b[2], a2);
            fma2(Q2a, tq2a[3], a3); fma2(Q2b, tq2b[3], a3);

            ull R2a = mul2(E2a, Q2a);
            ull R2b = mul2(E2b, Q2b);

            fma2(VA0, R2a, a0); fma2(VB0, R2b, a0);
            fma2(VA1, R2a, a1); fma2(VB1, R2b, a1);
            fma2(VA2, R2a, a2); fma2(VB2, R2b, a2);
            fma2(VA3, R2a, a3); fma2(VB3, R2b, a3);
            fma2(VAc, R2a, cU); fma2(VBc, R2b, cU);
        }
        // reduce packed accumulators — edge A
        {
            float l, hi, v0, v1, v2, v3, vc;
            upk2(l, hi, VA0); v0 = l + hi;
            upk2(l, hi, VA1); v1 = l + hi;
            upk2(l, hi, VA2); v2 = l + hi;
            upk2(l, hi, VA3); v3 = l + hi;
            upk2(l, hi, VAc); vc = l + hi;
            float sc = vc;
            sc = fmaf(tsA[0], v0, sc); sc = fmaf(tsA[1], v1, sc);
            sc = fmaf(tsA[2], v2, sc); sc = fmaf(tsA[3], v3, sc);
            sc *= 0.25f;
            sc = fminf(fmaxf(sc, -5.0f), 5.0f);
            float w = __expf(sc);
            zaccA[h] = w;
            red_add_v4(uzA + h * 4,
                       make_float4(tsA[0] * w, tsA[1] * w, tsA[2] * w, tsA[3] * w));
        }
        // edge B
        {
            float l, hi, v0, v1, v2, v3, vc;
            upk2(l, hi, VB0); v0 = l + hi;
            upk2(l, hi, VB1); v1 = l + hi;
            upk2(l, hi, VB2); v2 = l + hi;
            upk2(l, hi, VB3); v3 = l + hi;
            upk2(l, hi, VBc); vc = l + hi;
            float sc = vc;
            sc = fmaf(tsB[0], v0, sc); sc = fmaf(tsB[1], v1, sc);
            sc = fmaf(tsB[2], v2, sc); sc = fmaf(tsB[3], v3, sc);
            sc *= 0.25f;
            sc = fminf(fmaxf(sc, -5.0f), 5.0f);
            float w = __expf(sc);
            zaccB[h] = w;
            red_add_v4(uzB + h * 4,
                       make_float4(tsB[0] * w, tsB[1] * w, tsB[2] * w, tsB[3] * w));
        }
    }
    red_add_v4(uzA + 16, make_float4(zaccA[0], zaccA[1], zaccA[2], zaccA[3]));
    red_add_v4(uzB + 16, make_float4(zaccB[0], zaccB[1], zaccB[2], zaccB[3]));
}

// ---------------------------------------------------------------------------
// Kernel C: wV_d = A[:,d].U_h + c_d*Z_h ; h_d = wV_d/(Z_h+1e-6);
//           out = elu(h @ Wout + bout) @ Wout1 + bout1
// ---------------------------------------------------------------------------
__global__ __launch_bounds__(256)
void out_kernel(float* __restrict__ out,
                const float* __restrict__ Wout,  const float* __restrict__ bout,
                const float* __restrict__ Wout1, const float* __restrict__ bout1) {
    __shared__ float sWo[1024], sbo[16], sW1[16], sb1, sA[256], sc_[64];
    int t = threadIdx.x;
    for (int i = t; i < 1024; i += blockDim.x) sWo[i] = Wout[i];
    if (t < 16) { sbo[t] = bout[t]; sW1[t] = Wout1[t]; }
    if (t == 0) sb1 = bout1[0];
    if (t < 256) sA[t] = g_A[t];
    if (t < 64)  sc_[t] = g_c[t];
    __syncthreads();

    int m = blockIdx.x * blockDim.x + t;
    if (m >= M_NODES) return;

    const float4* uz4 = reinterpret_cast<const float4*>(g_UZ + (size_t)m * 20);
    float4 U0 = uz4[0], U1 = uz4[1], U2 = uz4[2], U3 = uz4[3], Zv = uz4[4];
    float U[NHEADS][4] = {
        {U0.x, U0.y, U0.z, U0.w}, {U1.x, U1.y, U1.z, U1.w},
        {U2.x, U2.y, U2.z, U2.w}, {U3.x, U3.y, U3.z, U3.w}};
    float Z[NHEADS] = {Zv.x, Zv.y, Zv.z, Zv.w};

    float acc[16];
#pragma unroll
    for (int k = 0; k < 16; k++) acc[k] = sbo[k];

#pragma unroll
    for (int h = 0; h < NHEADS; h++) {
        float rz = 1.0f / (Z[h] + 1e-6f);
#pragma unroll
        for (int dd = 0; dd < 16; dd++) {
            int d = h * 16 + dd;
            float wv = sc_[d] * Z[h];
#pragma unroll
            for (int i = 0; i < 4; i++) wv = fmaf(sA[d * 4 + i], U[h][i], wv);
            float hv = wv * rz;
#pragma unroll
            for (int k = 0; k < 16; k++) acc[k] = fmaf(hv, sWo[d * 16 + k], acc[k]);
        }
    }

    float val = sb1;
#pragma unroll
    for (int k = 0; k < 16; k++) {
        float a = elu1(acc[k]);
        val = fmaf(a, sW1[k], val);
    }
    out[m] = val;
}

// ---------------------------------------------------------------------------
extern "C" void kernel_launch(void* const* d_in, const int* in_sizes, int n_in,
                              void* d_out, int out_size) {
    // order: node_attr, edge_index, edge_feature, edge_vector,
    //        W1, b1, W2, b2, W, b, Wout, bout, Wout1, bout1
    const void*  ei   = d_in[1];
    const float* ef   = (const float*)d_in[2];
    const float* ev   = (const float*)d_in[3];
    const float* W1   = (const float*)d_in[4];
    const float* b1   = (const float*)d_in[5];
    const float* W2   = (const float*)d_in[6];
    const float* b2   = (const float*)d_in[7];
    const float* W    = (const float*)d_in[8];
    const float* b    = (const float*)d_in[9];
    const float* Wout = (const float*)d_in[10];
    const float* bout = (const float*)d_in[11];
    const float* Wout1= (const float*)d_in[12];
    const float* bout1= (const float*)d_in[13];
    float* out = (float*)d_out;

    probe_idx_kernel<<<1, 1>>>((const int*)ei);
    setup_kernel<<<1, 256>>>(W2, b2, W, b);
    t4_kernel<<<(M_NODES + 255) / 256, 256>>>(ev, W1, b1);
    edge_kernel<<<(NE_HALF + 127) / 128, 128>>>(ei, ef, W2, b2);
    out_kernel<<<(M_NODES + 255) / 256, 256>>>(out, Wout, bout, Wout1, bout1);
}